// round 1
// baseline (speedup 1.0000x reference)
#include <cuda_runtime.h>

// Problem constants (fixed instance: B=2048, T=2048, H=51)
#define H_  51
#define HP  52          // padded hidden
#define JP  208         // 4*HP padded gate count
#define RR  16          // batch rows per CTA
#define NT  416         // threads per CTA (13 warps)
#define TT  2048
#define BB  2048
#define PSTRIDE 20      // smem partial stride (conflict-free for float4 stores)

// Repacked weights (device globals; prep kernel fills them each launch)
__device__ float g_W1p[HP*JP];   // [k][j] layer-1 W_hh, padded
__device__ float g_W2a[HP*JP];   // [k][j] layer-2 W_ih
__device__ float g_W2b[HP*JP];   // [k][j] layer-2 W_hh
__device__ float g_b1[JP];
__device__ float g_wx[JP];
__device__ float g_b2[JP];
__device__ float g_wlin[HP];
__device__ float g_blin[1];

__global__ void prep_kernel(const float* __restrict__ W_ih1, const float* __restrict__ W_hh1,
                            const float* __restrict__ b_ih1, const float* __restrict__ b_hh1,
                            const float* __restrict__ W_ih2, const float* __restrict__ W_hh2,
                            const float* __restrict__ b_ih2, const float* __restrict__ b_hh2,
                            const float* __restrict__ W_lin, const float* __restrict__ b_lin)
{
    int stride = gridDim.x * blockDim.x;
    int i0 = blockIdx.x * blockDim.x + threadIdx.x;
    for (int idx = i0; idx < HP*JP; idx += stride) {
        int k = idx / JP, j = idx % JP;
        int g = j / HP, n = j % HP;
        bool v = (n < H_) && (k < H_);
        int ro = g*H_ + n;
        g_W1p[idx] = v ? W_hh1[ro*H_ + k] : 0.f;
        g_W2a[idx] = v ? W_ih2[ro*H_ + k] : 0.f;
        g_W2b[idx] = v ? W_hh2[ro*H_ + k] : 0.f;
    }
    for (int j = i0; j < JP; j += stride) {
        int g = j / HP, n = j % HP;
        bool v = (n < H_);
        int ro = g*H_ + n;
        g_b1[j] = v ? (b_ih1[ro] + b_hh1[ro]) : 0.f;
        g_wx[j] = v ? W_ih1[ro] : 0.f;
        g_b2[j] = v ? (b_ih2[ro] + b_hh2[ro]) : 0.f;
    }
    for (int n = i0; n < HP; n += stride) g_wlin[n] = (n < H_) ? W_lin[n] : 0.f;
    if (i0 == 0) g_blin[0] = b_lin[0];
}

__device__ __forceinline__ float sigf(float x) {
    return __fdividef(1.f, 1.f + __expf(-x));
}
__device__ __forceinline__ float tanhf_(float x) {
    return __fdividef(2.f, 1.f + __expf(-2.f*x)) - 1.f;
}

__global__ __launch_bounds__(NT, 1)
void lstm_kernel(const float* __restrict__ input, float* __restrict__ out)
{
    extern __shared__ float sm[];
    float* p1  = sm;                   // 2*JP*PSTRIDE = 8320 floats
    float* p2  = p1 + 2*JP*PSTRIDE;    // 8320
    float* h1s = p2 + 2*JP*PSTRIDE;    // HP*RR = 832   layout [k][r]
    float* h2s = h1s + HP*RR;          // 832
    float* xs  = h2s + HP*RR;          // RR
    float* wls = xs + RR;              // HP
    float* b2s = wls + HP;             // JP

    const int tid  = threadIdx.x;
    const int row0 = blockIdx.x * RR;

    // phase-1 task: gate row j1, k-half `half` (26 k's)
    const int j1 = tid >> 1, half = tid & 1;
    // phase-2 task: gate row j2, src 0 = W_ih2 (h1), 1 = W_hh2 (h2)
    const int src = (tid >= JP) ? 1 : 0;
    const int j2  = tid - src*JP;
    // update task: cells un and un+26, row ur
    const int un = tid >> 4, ur = tid & 15;

    // register-resident weights
    float w1[26];
#pragma unroll
    for (int kk = 0; kk < 26; kk++)
        w1[kk] = g_W1p[(half*26 + kk)*JP + j1];
    float w2[HP];
    {
        const float* Ws = src ? g_W2b : g_W2a;
#pragma unroll
        for (int k = 0; k < HP; k++) w2[k] = Ws[k*JP + j2];
    }
    const float bias1 = g_b1[j1];
    const float wx    = g_wx[j1];
    const float blin  = g_blin[0];

    // cell state in registers of update threads
    float c1a = 0.f, c1b = 0.f, c2a = 0.f, c2b = 0.f;

    for (int i = tid; i < HP*RR; i += NT) { h1s[i] = 0.f; h2s[i] = 0.f; }
    for (int i = tid; i < HP; i += NT) wls[i] = g_wlin[i];
    for (int i = tid; i < JP; i += NT) b2s[i] = g_b2[i];
    if (tid >= RR && tid < 2*RR) xs[tid - RR] = input[(row0 + tid - RR)*TT + 0];
    __syncthreads();

    for (int t = 0; t < TT; t++) {
        // prefetch next x early (long-latency LDG hidden behind the step)
        float xnext = 0.f;
        if (tid >= RR && tid < 2*RR && (t + 1) < TT)
            xnext = __ldg(&input[(row0 + tid - RR)*TT + t + 1]);

        // output for step t-1 (threads 0..15; h2s stable until update2)
        if (tid < RR && t > 0) {
            float s0 = 0.f, s1 = 0.f, s2 = 0.f, s3 = 0.f;
#pragma unroll
            for (int n = 0; n < HP; n += 4) {
                s0 = fmaf(wls[n+0], h2s[(n+0)*RR + tid], s0);
                s1 = fmaf(wls[n+1], h2s[(n+1)*RR + tid], s1);
                s2 = fmaf(wls[n+2], h2s[(n+2)*RR + tid], s2);
                s3 = fmaf(wls[n+3], h2s[(n+3)*RR + tid], s3);
            }
            out[(row0 + tid)*TT + (t - 1)] = (s0 + s1) + (s2 + s3) + blin;
        }

        // ---- phase 1: half-dots of gates1 over 16 rows ----
        {
            float acc[RR];
            if (half == 0) {
#pragma unroll
                for (int r = 0; r < RR; r++) acc[r] = fmaf(wx, xs[r], bias1);
            } else {
#pragma unroll
                for (int r = 0; r < RR; r++) acc[r] = 0.f;
            }
            const float4* hbase = reinterpret_cast<const float4*>(h1s + half*26*RR);
#pragma unroll
            for (int kk = 0; kk < 26; kk++) {
                float w = w1[kk];
#pragma unroll
                for (int rv = 0; rv < RR/4; rv++) {
                    float4 h = hbase[kk*(RR/4) + rv];
                    acc[rv*4+0] = fmaf(w, h.x, acc[rv*4+0]);
                    acc[rv*4+1] = fmaf(w, h.y, acc[rv*4+1]);
                    acc[rv*4+2] = fmaf(w, h.z, acc[rv*4+2]);
                    acc[rv*4+3] = fmaf(w, h.w, acc[rv*4+3]);
                }
            }
            float4* pw = reinterpret_cast<float4*>(p1 + tid*PSTRIDE);
#pragma unroll
            for (int rv = 0; rv < RR/4; rv++)
                pw[rv] = make_float4(acc[rv*4+0], acc[rv*4+1], acc[rv*4+2], acc[rv*4+3]);
        }
        __syncthreads();

        // ---- update 1: LSTM cell for (un, ur) and (un+26, ur) ----
        {
#pragma unroll
            for (int tsk = 0; tsk < 2; tsk++) {
                int n = un + tsk*26;
                float gi = p1[(2*(0*HP+n)+0)*PSTRIDE + ur] + p1[(2*(0*HP+n)+1)*PSTRIDE + ur];
                float gf = p1[(2*(1*HP+n)+0)*PSTRIDE + ur] + p1[(2*(1*HP+n)+1)*PSTRIDE + ur];
                float gg = p1[(2*(2*HP+n)+0)*PSTRIDE + ur] + p1[(2*(2*HP+n)+1)*PSTRIDE + ur];
                float go = p1[(2*(3*HP+n)+0)*PSTRIDE + ur] + p1[(2*(3*HP+n)+1)*PSTRIDE + ur];
                float c = tsk ? c1b : c1a;
                c = sigf(gf)*c + sigf(gi)*tanhf_(gg);
                if (tsk) c1b = c; else c1a = c;
                h1s[n*RR + ur] = sigf(go)*tanhf_(c);
            }
        }
        __syncthreads();

        // ---- phase 2: full 52-dot (W_ih2·h1new or W_hh2·h2) over 16 rows ----
        {
            float acc[RR];
#pragma unroll
            for (int r = 0; r < RR; r++) acc[r] = 0.f;
            const float4* hbase = reinterpret_cast<const float4*>(src ? h2s : h1s);
#pragma unroll
            for (int k = 0; k < HP; k++) {
                float w = w2[k];
#pragma unroll
                for (int rv = 0; rv < RR/4; rv++) {
                    float4 h = hbase[k*(RR/4) + rv];
                    acc[rv*4+0] = fmaf(w, h.x, acc[rv*4+0]);
                    acc[rv*4+1] = fmaf(w, h.y, acc[rv*4+1]);
                    acc[rv*4+2] = fmaf(w, h.z, acc[rv*4+2]);
                    acc[rv*4+3] = fmaf(w, h.w, acc[rv*4+3]);
                }
            }
            float4* pw = reinterpret_cast<float4*>(p2 + tid*PSTRIDE);
#pragma unroll
            for (int rv = 0; rv < RR/4; rv++)
                pw[rv] = make_float4(acc[rv*4+0], acc[rv*4+1], acc[rv*4+2], acc[rv*4+3]);
        }
        __syncthreads();

        // ---- update 2: cell for layer 2 (+ bias, partials from both sources) ----
        {
#pragma unroll
            for (int tsk = 0; tsk < 2; tsk++) {
                int n = un + tsk*26;
                float gi = p2[(0*HP+n)*PSTRIDE + ur] + p2[(JP+0*HP+n)*PSTRIDE + ur] + b2s[0*HP+n];
                float gf = p2[(1*HP+n)*PSTRIDE + ur] + p2[(JP+1*HP+n)*PSTRIDE + ur] + b2s[1*HP+n];
                float gg = p2[(2*HP+n)*PSTRIDE + ur] + p2[(JP+2*HP+n)*PSTRIDE + ur] + b2s[2*HP+n];
                float go = p2[(3*HP+n)*PSTRIDE + ur] + p2[(JP+3*HP+n)*PSTRIDE + ur] + b2s[3*HP+n];
                float c = tsk ? c2b : c2a;
                c = sigf(gf)*c + sigf(gi)*tanhf_(gg);
                if (tsk) c2b = c; else c2a = c;
                h2s[n*RR + ur] = sigf(go)*tanhf_(c);
            }
        }
        if (tid >= RR && tid < 2*RR && (t + 1) < TT) xs[tid - RR] = xnext;
        __syncthreads();
    }

    // final output column (t = TT-1)
    if (tid < RR) {
        float s0 = 0.f, s1 = 0.f, s2 = 0.f, s3 = 0.f;
#pragma unroll
        for (int n = 0; n < HP; n += 4) {
            s0 = fmaf(wls[n+0], h2s[(n+0)*RR + tid], s0);
            s1 = fmaf(wls[n+1], h2s[(n+1)*RR + tid], s1);
            s2 = fmaf(wls[n+2], h2s[(n+2)*RR + tid], s2);
            s3 = fmaf(wls[n+3], h2s[(n+3)*RR + tid], s3);
        }
        out[(row0 + tid)*TT + (TT - 1)] = (s0 + s1) + (s2 + s3) + blin;
    }
}

extern "C" void kernel_launch(void* const* d_in, const int* in_sizes, int n_in,
                              void* d_out, int out_size)
{
    const float* input = (const float*)d_in[0];
    const float* W_ih1 = (const float*)d_in[1];
    const float* W_hh1 = (const float*)d_in[2];
    const float* b_ih1 = (const float*)d_in[3];
    const float* b_hh1 = (const float*)d_in[4];
    const float* W_ih2 = (const float*)d_in[5];
    const float* W_hh2 = (const float*)d_in[6];
    const float* b_ih2 = (const float*)d_in[7];
    const float* b_hh2 = (const float*)d_in[8];
    const float* W_lin = (const float*)d_in[9];
    const float* b_lin = (const float*)d_in[10];
    float* out = (float*)d_out;

    const int smem_bytes = (2*JP*PSTRIDE*2 + HP*RR*2 + RR + HP + JP) * (int)sizeof(float);
    cudaFuncSetAttribute(lstm_kernel, cudaFuncAttributeMaxDynamicSharedMemorySize, smem_bytes);

    prep_kernel<<<64, 256>>>(W_ih1, W_hh1, b_ih1, b_hh1,
                             W_ih2, W_hh2, b_ih2, b_hh2, W_lin, b_lin);
    lstm_kernel<<<BB/RR, NT, smem_bytes>>>(input, out);
}

// round 2
// speedup vs baseline: 1.0640x; 1.0640x over previous
#include <cuda_runtime.h>

// Problem constants (fixed instance: B=2048, T=2048, H=51)
#define H_  51
#define HP  52          // padded hidden
#define JP  208         // 4*HP padded gate count
#define RR  16          // batch rows per CTA
#define NT  416         // threads per CTA (13 warps)
#define TT  2048
#define BB  2048
#define PSTRIDE 20      // smem partial stride (conflict-free for float4 stores)

// Repacked weights (device globals; prep kernel fills them each launch)
__device__ float g_W1p[HP*JP];   // [k][j] layer-1 W_hh, padded
__device__ float g_W2a[HP*JP];   // [k][j] layer-2 W_ih
__device__ float g_W2b[HP*JP];   // [k][j] layer-2 W_hh
__device__ float g_b1[JP];
__device__ float g_wx[JP];
__device__ float g_b2[JP];
__device__ float g_wlin[HP];
__device__ float g_blin[1];

__global__ void prep_kernel(const float* __restrict__ W_ih1, const float* __restrict__ W_hh1,
                            const float* __restrict__ b_ih1, const float* __restrict__ b_hh1,
                            const float* __restrict__ W_ih2, const float* __restrict__ W_hh2,
                            const float* __restrict__ b_ih2, const float* __restrict__ b_hh2,
                            const float* __restrict__ W_lin, const float* __restrict__ b_lin)
{
    int stride = gridDim.x * blockDim.x;
    int i0 = blockIdx.x * blockDim.x + threadIdx.x;
    for (int idx = i0; idx < HP*JP; idx += stride) {
        int k = idx / JP, j = idx % JP;
        int g = j / HP, n = j % HP;
        bool v = (n < H_) && (k < H_);
        int ro = g*H_ + n;
        g_W1p[idx] = v ? W_hh1[ro*H_ + k] : 0.f;
        g_W2a[idx] = v ? W_ih2[ro*H_ + k] : 0.f;
        g_W2b[idx] = v ? W_hh2[ro*H_ + k] : 0.f;
    }
    for (int j = i0; j < JP; j += stride) {
        int g = j / HP, n = j % HP;
        bool v = (n < H_);
        int ro = g*H_ + n;
        g_b1[j] = v ? (b_ih1[ro] + b_hh1[ro]) : 0.f;
        g_wx[j] = v ? W_ih1[ro] : 0.f;
        g_b2[j] = v ? (b_ih2[ro] + b_hh2[ro]) : 0.f;
    }
    for (int n = i0; n < HP; n += stride) g_wlin[n] = (n < H_) ? W_lin[n] : 0.f;
    if (i0 == 0) g_blin[0] = b_lin[0];
}

__device__ __forceinline__ float sigf(float x) {
    return __fdividef(1.f, 1.f + __expf(-x));
}
__device__ __forceinline__ float tanhf_(float x) {
    return __fdividef(2.f, 1.f + __expf(-2.f*x)) - 1.f;
}

// ---- packed f32x2 helpers (ptxas will not auto-fuse; PTX-only path) ----
__device__ __forceinline__ unsigned long long pk2(float w) {
    unsigned long long r;
    asm("mov.b64 %0, {%1, %1};" : "=l"(r) : "f"(w));
    return r;
}
__device__ __forceinline__ void fma2(unsigned long long& a, unsigned long long w, unsigned long long h) {
    asm("fma.rn.f32x2 %0, %1, %2, %3;" : "=l"(a) : "l"(w), "l"(h), "l"(a));
}

__global__ __launch_bounds__(NT, 1)
void lstm_kernel(const float* __restrict__ input, float* __restrict__ out)
{
    extern __shared__ float sm[];
    float* p1  = sm;                   // 2*JP*PSTRIDE = 8320 floats
    float* p2  = p1 + 2*JP*PSTRIDE;    // 8320
    float* h1s = p2 + 2*JP*PSTRIDE;    // HP*RR = 832   layout [k][r]
    float* h2s = h1s + HP*RR;          // 832
    float* xs  = h2s + HP*RR;          // RR
    float* wls = xs + RR;              // HP
    float* b2s = wls + HP;             // JP

    const int tid  = threadIdx.x;
    const int row0 = blockIdx.x * RR;

    // phase-1 task: gate row j1, k-half `half` (26 k's)
    const int j1 = tid >> 1, half = tid & 1;
    // phase-2 task: gate row j2, src 0 = W_ih2 (h1), 1 = W_hh2 (h2)
    const int src = (tid >= JP) ? 1 : 0;
    const int j2  = tid - src*JP;
    // update task: cells un and un+26, row ur
    const int un = tid >> 4, ur = tid & 15;

    // register-resident weights
    float w1[26];
#pragma unroll
    for (int kk = 0; kk < 26; kk++)
        w1[kk] = g_W1p[(half*26 + kk)*JP + j1];
    float w2[HP];
    {
        const float* Ws = src ? g_W2b : g_W2a;
#pragma unroll
        for (int k = 0; k < HP; k++) w2[k] = Ws[k*JP + j2];
    }
    const float bias1 = g_b1[j1];
    const float wx    = g_wx[j1];
    const float blin  = g_blin[0];

    // cell state in registers of update threads
    float c1a = 0.f, c1b = 0.f, c2a = 0.f, c2b = 0.f;

    for (int i = tid; i < HP*RR; i += NT) { h1s[i] = 0.f; h2s[i] = 0.f; }
    for (int i = tid; i < HP; i += NT) wls[i] = g_wlin[i];
    for (int i = tid; i < JP; i += NT) b2s[i] = g_b2[i];
    if (tid >= RR && tid < 2*RR) xs[tid - RR] = input[(row0 + tid - RR)*TT + 0];
    __syncthreads();

    for (int t = 0; t < TT; t++) {
        // prefetch next x early (long-latency LDG hidden behind the step)
        float xnext = 0.f;
        if (tid >= RR && tid < 2*RR && (t + 1) < TT)
            xnext = __ldg(&input[(row0 + tid - RR)*TT + t + 1]);

        // output for step t-1 (threads 0..15; h2s stable until update2)
        if (tid < RR && t > 0) {
            float s0 = 0.f, s1 = 0.f, s2 = 0.f, s3 = 0.f;
#pragma unroll
            for (int n = 0; n < HP; n += 4) {
                s0 = fmaf(wls[n+0], h2s[(n+0)*RR + tid], s0);
                s1 = fmaf(wls[n+1], h2s[(n+1)*RR + tid], s1);
                s2 = fmaf(wls[n+2], h2s[(n+2)*RR + tid], s2);
                s3 = fmaf(wls[n+3], h2s[(n+3)*RR + tid], s3);
            }
            out[(row0 + tid)*TT + (t - 1)] = (s0 + s1) + (s2 + s3) + blin;
        }

        // ---- phase 1: half-dots of gates1 over 16 rows (f32x2 packed) ----
        {
            unsigned long long acc[RR/2];
            if (half == 0) {
                unsigned long long wxp = pk2(wx);
                unsigned long long b1p = pk2(bias1);
                const ulonglong2* xv = reinterpret_cast<const ulonglong2*>(xs);
#pragma unroll
                for (int rv = 0; rv < RR/4; rv++) {
                    ulonglong2 x2 = xv[rv];
                    acc[2*rv+0] = b1p; fma2(acc[2*rv+0], wxp, x2.x);
                    acc[2*rv+1] = b1p; fma2(acc[2*rv+1], wxp, x2.y);
                }
            } else {
#pragma unroll
                for (int r = 0; r < RR/2; r++) acc[r] = 0ULL;
            }
            const ulonglong2* hbase = reinterpret_cast<const ulonglong2*>(h1s + half*26*RR);
#pragma unroll
            for (int kk = 0; kk < 26; kk++) {
                unsigned long long w = pk2(w1[kk]);
#pragma unroll
                for (int rv = 0; rv < RR/4; rv++) {
                    ulonglong2 h = hbase[kk*(RR/4) + rv];
                    fma2(acc[2*rv+0], w, h.x);
                    fma2(acc[2*rv+1], w, h.y);
                }
            }
            ulonglong2* pw = reinterpret_cast<ulonglong2*>(p1 + tid*PSTRIDE);
#pragma unroll
            for (int rv = 0; rv < RR/4; rv++) {
                ulonglong2 v; v.x = acc[2*rv+0]; v.y = acc[2*rv+1];
                pw[rv] = v;
            }
        }
        __syncthreads();

        // ---- update 1: LSTM cell for (un, ur) and (un+26, ur) ----
        {
#pragma unroll
            for (int tsk = 0; tsk < 2; tsk++) {
                int n = un + tsk*26;
                float gi = p1[(2*(0*HP+n)+0)*PSTRIDE + ur] + p1[(2*(0*HP+n)+1)*PSTRIDE + ur];
                float gf = p1[(2*(1*HP+n)+0)*PSTRIDE + ur] + p1[(2*(1*HP+n)+1)*PSTRIDE + ur];
                float gg = p1[(2*(2*HP+n)+0)*PSTRIDE + ur] + p1[(2*(2*HP+n)+1)*PSTRIDE + ur];
                float go = p1[(2*(3*HP+n)+0)*PSTRIDE + ur] + p1[(2*(3*HP+n)+1)*PSTRIDE + ur];
                float c = tsk ? c1b : c1a;
                c = sigf(gf)*c + sigf(gi)*tanhf_(gg);
                if (tsk) c1b = c; else c1a = c;
                h1s[n*RR + ur] = sigf(go)*tanhf_(c);
            }
        }
        __syncthreads();

        // ---- phase 2: full 52-dot (W_ih2·h1new or W_hh2·h2) over 16 rows (f32x2) ----
        {
            unsigned long long acc[RR/2];
#pragma unroll
            for (int r = 0; r < RR/2; r++) acc[r] = 0ULL;
            const ulonglong2* hbase = reinterpret_cast<const ulonglong2*>(src ? h2s : h1s);
#pragma unroll
            for (int k = 0; k < HP; k++) {
                unsigned long long w = pk2(w2[k]);
#pragma unroll
                for (int rv = 0; rv < RR/4; rv++) {
                    ulonglong2 h = hbase[k*(RR/4) + rv];
                    fma2(acc[2*rv+0], w, h.x);
                    fma2(acc[2*rv+1], w, h.y);
                }
            }
            ulonglong2* pw = reinterpret_cast<ulonglong2*>(p2 + tid*PSTRIDE);
#pragma unroll
            for (int rv = 0; rv < RR/4; rv++) {
                ulonglong2 v; v.x = acc[2*rv+0]; v.y = acc[2*rv+1];
                pw[rv] = v;
            }
        }
        __syncthreads();

        // ---- update 2: cell for layer 2 (+ bias, partials from both sources) ----
        {
#pragma unroll
            for (int tsk = 0; tsk < 2; tsk++) {
                int n = un + tsk*26;
                float gi = p2[(0*HP+n)*PSTRIDE + ur] + p2[(JP+0*HP+n)*PSTRIDE + ur] + b2s[0*HP+n];
                float gf = p2[(1*HP+n)*PSTRIDE + ur] + p2[(JP+1*HP+n)*PSTRIDE + ur] + b2s[1*HP+n];
                float gg = p2[(2*HP+n)*PSTRIDE + ur] + p2[(JP+2*HP+n)*PSTRIDE + ur] + b2s[2*HP+n];
                float go = p2[(3*HP+n)*PSTRIDE + ur] + p2[(JP+3*HP+n)*PSTRIDE + ur] + b2s[3*HP+n];
                float c = tsk ? c2b : c2a;
                c = sigf(gf)*c + sigf(gi)*tanhf_(gg);
                if (tsk) c2b = c; else c2a = c;
                h2s[n*RR + ur] = sigf(go)*tanhf_(c);
            }
        }
        if (tid >= RR && tid < 2*RR && (t + 1) < TT) xs[tid - RR] = xnext;
        __syncthreads();
    }

    // final output column (t = TT-1)
    if (tid < RR) {
        float s0 = 0.f, s1 = 0.f, s2 = 0.f, s3 = 0.f;
#pragma unroll
        for (int n = 0; n < HP; n += 4) {
            s0 = fmaf(wls[n+0], h2s[(n+0)*RR + tid], s0);
            s1 = fmaf(wls[n+1], h2s[(n+1)*RR + tid], s1);
            s2 = fmaf(wls[n+2], h2s[(n+2)*RR + tid], s2);
            s3 = fmaf(wls[n+3], h2s[(n+3)*RR + tid], s3);
        }
        out[(row0 + tid)*TT + (TT - 1)] = (s0 + s1) + (s2 + s3) + blin;
    }
}

extern "C" void kernel_launch(void* const* d_in, const int* in_sizes, int n_in,
                              void* d_out, int out_size)
{
    const float* input = (const float*)d_in[0];
    const float* W_ih1 = (const float*)d_in[1];
    const float* W_hh1 = (const float*)d_in[2];
    const float* b_ih1 = (const float*)d_in[3];
    const float* b_hh1 = (const float*)d_in[4];
    const float* W_ih2 = (const float*)d_in[5];
    const float* W_hh2 = (const float*)d_in[6];
    const float* b_ih2 = (const float*)d_in[7];
    const float* b_hh2 = (const float*)d_in[8];
    const float* W_lin = (const float*)d_in[9];
    const float* b_lin = (const float*)d_in[10];
    float* out = (float*)d_out;

    const int smem_bytes = (2*JP*PSTRIDE*2 + HP*RR*2 + RR + HP + JP) * (int)sizeof(float);
    cudaFuncSetAttribute(lstm_kernel, cudaFuncAttributeMaxDynamicSharedMemorySize, smem_bytes);

    prep_kernel<<<64, 256>>>(W_ih1, W_hh1, b_ih1, b_hh1,
                             W_ih2, W_hh2, b_ih2, b_hh2, W_lin, b_lin);
    lstm_kernel<<<BB/RR, NT, smem_bytes>>>(input, out);
}